// round 1
// baseline (speedup 1.0000x reference)
#include <cuda_runtime.h>
#include <mma.h>
#include <math.h>

#define NATOMS 1048576
#define BMOL   16384
#define DIM    128
#define STEPS  8

#define ATT_THREADS 256
#define SMAX  176      // atoms cached in dynamic SMEM per block (P(cnt>176) ~ 0 for Poisson(64))
#define SCMAX 2048     // scores held in static SMEM up to this count

// ---------------- scratch (static device allocations only) ----------------
__device__ float g_carry[BMOL * DIM];          // 8 MB
__device__ float g_mem  [BMOL * DIM];          // 8 MB
__device__ float g_cse  [BMOL * 2 * DIM];      // 16 MB
__device__ float g_z    [BMOL * 4 * DIM];      // 32 MB
__device__ int   g_segstart[BMOL + 1];
__device__ float g_scores[NATOMS];             // fallback if a segment is huge

// ---------------- init ----------------
__global__ void init_state() {
    int i = blockIdx.x * blockDim.x + threadIdx.x;
    if (i < BMOL * DIM) { g_carry[i] = 0.f; g_mem[i] = 0.f; }
}

// seg_start[b] = lower_bound(idx, b); idx is sorted
__global__ void seg_start_kernel(const int* __restrict__ idx) {
    int b = blockIdx.x * blockDim.x + threadIdx.x;
    if (b > BMOL) return;
    int lo = 0, hi = NATOMS;
    while (lo < hi) {
        int mid = (lo + hi) >> 1;
        if (idx[mid] < b) lo = mid + 1; else hi = mid;
    }
    g_segstart[b] = lo;
}

// ---------------- fused per-molecule attention ----------------
// one block per molecule: load segment atoms into SMEM once, compute scores,
// segment softmax, readout; write cse row = [carry | readout]
__global__ void __launch_bounds__(ATT_THREADS) attn_kernel(
    const float4* __restrict__ F4, float* __restrict__ out) {
    int b    = blockIdx.x;
    int tid  = threadIdx.x;
    int lane = tid & 31;
    int wid  = tid >> 5;

    __shared__ float  carry_s[DIM];
    __shared__ float  sc_s[SCMAX];
    __shared__ __align__(16) float4 part[8][32];   // per-warp readout partials
    __shared__ float  red[8];
    __shared__ float  bc[2];
    extern __shared__ float4 Fs[];                 // SMAX * 32 float4

    int s = g_segstart[b];
    int e = g_segstart[b + 1];
    int cnt = e - s;

    if (tid < DIM) carry_s[tid] = g_carry[b * DIM + tid];
    __syncthreads();

    if (cnt <= 0) {  // empty segment: readout = 0
        if (tid < DIM) out[(size_t)b * 2 * DIM + tid] = carry_s[tid];
        else           out[(size_t)b * 2 * DIM + tid] = 0.f;
        return;
    }

    bool cached = (cnt <= SMAX);
    if (cached) {
        int tot = cnt * 32;
        for (int i = tid; i < tot; i += ATT_THREADS)
            Fs[i] = F4[(size_t)s * 32 + i];
    }
    float* sc = (cnt <= SCMAX) ? sc_s : (g_scores + s);
    __syncthreads();

    float4 c4 = ((const float4*)carry_s)[lane];

    // scores: one warp per atom
    for (int a = wid; a < cnt; a += 8) {
        float4 f = cached ? Fs[a * 32 + lane] : F4[(size_t)(s + a) * 32 + lane];
        float v = f.x * c4.x + f.y * c4.y + f.z * c4.z + f.w * c4.w;
        #pragma unroll
        for (int o = 16; o > 0; o >>= 1) v += __shfl_xor_sync(0xffffffffu, v, o);
        if (lane == 0) sc[a] = v;
    }
    __syncthreads();

    // segment max
    float m = -INFINITY;
    for (int i = tid; i < cnt; i += ATT_THREADS) m = fmaxf(m, sc[i]);
    #pragma unroll
    for (int o = 16; o > 0; o >>= 1) m = fmaxf(m, __shfl_xor_sync(0xffffffffu, m, o));
    if (lane == 0) red[wid] = m;
    __syncthreads();
    if (tid == 0) {
        float mm = red[0];
        #pragma unroll
        for (int w = 1; w < 8; w++) mm = fmaxf(mm, red[w]);
        bc[0] = mm;
    }
    __syncthreads();
    float smax = bc[0];

    // exp + segment sum
    float ssum = 0.f;
    for (int i = tid; i < cnt; i += ATT_THREADS) {
        float ev = expf(sc[i] - smax);
        sc[i] = ev;
        ssum += ev;
    }
    #pragma unroll
    for (int o = 16; o > 0; o >>= 1) ssum += __shfl_xor_sync(0xffffffffu, ssum, o);
    if (lane == 0) red[wid] = ssum;
    __syncthreads();
    if (tid == 0) {
        float t = 0.f;
        #pragma unroll
        for (int w = 0; w < 8; w++) t += red[w];
        bc[1] = t;
    }
    __syncthreads();
    float inv = 1.0f / bc[1];

    // readout: warp-strided accumulation over atoms
    float4 acc = make_float4(0.f, 0.f, 0.f, 0.f);
    for (int a = wid; a < cnt; a += 8) {
        float  co = sc[a] * inv;
        float4 f  = cached ? Fs[a * 32 + lane] : F4[(size_t)(s + a) * 32 + lane];
        acc.x += co * f.x; acc.y += co * f.y; acc.z += co * f.z; acc.w += co * f.w;
    }
    part[wid][lane] = acc;
    __syncthreads();

    if (tid < DIM) {
        out[(size_t)b * 2 * DIM + tid] = carry_s[tid];
    } else {
        int d = tid - DIM;                         // 0..127
        const float* pf = (const float*)part;      // [8][128]
        float sum = 0.f;
        #pragma unroll
        for (int w = 0; w < 8; w++) sum += pf[w * 128 + d];
        out[(size_t)b * 2 * DIM + DIM + d] = sum;
    }
}

// ---------------- 3xTF32 GEMM: g_z = X[BMOL,256] @ W[256,512] ----------------
using namespace nvcuda;
#define GEMM_THREADS 128

__global__ void __launch_bounds__(GEMM_THREADS) gemm_kernel(
    const float* __restrict__ X, const float* __restrict__ W) {
    int bm = blockIdx.x * 64;
    int bn = blockIdx.y * 64;

    __shared__ __align__(16) float Ah[64][36], Al[64][36];
    __shared__ __align__(16) float Bh[32][72], Bl[32][72];

    wmma::fragment<wmma::accumulator, 16, 16, 8, float> acc[2][2];
    #pragma unroll
    for (int i = 0; i < 2; i++)
        #pragma unroll
        for (int j = 0; j < 2; j++) wmma::fill_fragment(acc[i][j], 0.f);

    int wid = threadIdx.x >> 5;
    int wm = (wid >> 1) * 32;
    int wn = (wid & 1) * 32;

    for (int k0 = 0; k0 < 256; k0 += 32) {
        for (int i = threadIdx.x; i < 64 * 32; i += GEMM_THREADS) {
            int r = i >> 5, c = i & 31;
            float v = X[(size_t)(bm + r) * 256 + k0 + c];
            float h = wmma::__float_to_tf32(v);
            Ah[r][c] = h;
            Al[r][c] = wmma::__float_to_tf32(v - h);
        }
        for (int i = threadIdx.x; i < 32 * 64; i += GEMM_THREADS) {
            int r = i >> 6, c = i & 63;
            float v = W[(size_t)(k0 + r) * 512 + bn + c];
            float h = wmma::__float_to_tf32(v);
            Bh[r][c] = h;
            Bl[r][c] = wmma::__float_to_tf32(v - h);
        }
        __syncthreads();

        #pragma unroll
        for (int kk = 0; kk < 32; kk += 8) {
            wmma::fragment<wmma::matrix_a, 16, 16, 8, wmma::precision::tf32, wmma::row_major> ah[2], al[2];
            wmma::fragment<wmma::matrix_b, 16, 16, 8, wmma::precision::tf32, wmma::row_major> bh[2], bl[2];
            #pragma unroll
            for (int i = 0; i < 2; i++) {
                wmma::load_matrix_sync(ah[i], &Ah[wm + i * 16][kk], 36);
                wmma::load_matrix_sync(al[i], &Al[wm + i * 16][kk], 36);
            }
            #pragma unroll
            for (int j = 0; j < 2; j++) {
                wmma::load_matrix_sync(bh[j], &Bh[kk][wn + j * 16], 72);
                wmma::load_matrix_sync(bl[j], &Bl[kk][wn + j * 16], 72);
            }
            #pragma unroll
            for (int i = 0; i < 2; i++)
                #pragma unroll
                for (int j = 0; j < 2; j++) {
                    wmma::mma_sync(acc[i][j], ah[i], bh[j], acc[i][j]);
                    wmma::mma_sync(acc[i][j], ah[i], bl[j], acc[i][j]);
                    wmma::mma_sync(acc[i][j], al[i], bh[j], acc[i][j]);
                }
        }
        __syncthreads();
    }

    #pragma unroll
    for (int i = 0; i < 2; i++)
        #pragma unroll
        for (int j = 0; j < 2; j++)
            wmma::store_matrix_sync(&g_z[(size_t)(bm + wm + i * 16) * 512 + bn + wn + j * 16],
                                    acc[i][j], 512, wmma::mem_row_major);
}

// ---------------- LSTM pointwise ----------------
__global__ void lstm_kernel(const float* __restrict__ bias) {
    int i = blockIdx.x * blockDim.x + threadIdx.x;
    if (i >= BMOL * DIM) return;
    int b = i >> 7;
    int j = i & 127;
    const float* zr = g_z + (size_t)b * 512;
    float u = zr[j]       + bias[j];
    float f = zr[128 + j] + bias[128 + j];
    float c = zr[256 + j] + bias[256 + j];
    float o = zr[384 + j] + bias[384 + j];
    float su = 1.f / (1.f + expf(-u));
    float sf = 1.f / (1.f + expf(-f));
    float so = 1.f / (1.f + expf(-o));
    float mem = sf * g_mem[i] + su * tanhf(c);
    g_mem[i]   = mem;
    g_carry[i] = so * tanhf(mem);
}

// ---------------- launch ----------------
extern "C" void kernel_launch(void* const* d_in, const int* in_sizes, int n_in,
                              void* d_out, int out_size) {
    const float* F    = (const float*)d_in[0];
    const int*   idx  = (const int*)d_in[1];
    const float* W    = (const float*)d_in[2];
    const float* bias = (const float*)d_in[3];
    float* out = (float*)d_out;

    cudaFuncSetAttribute(attn_kernel, cudaFuncAttributeMaxDynamicSharedMemorySize,
                         SMAX * 32 * (int)sizeof(float4));

    void* csep = nullptr;
    cudaGetSymbolAddress(&csep, g_cse);
    float* cse = (float*)csep;

    init_state<<<(BMOL * DIM + 255) / 256, 256>>>();
    seg_start_kernel<<<(BMOL + 1 + 255) / 256, 256>>>(idx);

    for (int t = 0; t < STEPS; t++) {
        float* o = (t == STEPS - 1) ? out : cse;
        attn_kernel<<<BMOL, ATT_THREADS, SMAX * 32 * sizeof(float4)>>>(
            (const float4*)F, o);
        if (t < STEPS - 1) {
            dim3 g(BMOL / 64, 512 / 64);
            gemm_kernel<<<g, GEMM_THREADS>>>(cse, W);
            lstm_kernel<<<(BMOL * DIM + 255) / 256, 256>>>(bias);
        }
    }
}

// round 2
// speedup vs baseline: 1.0217x; 1.0217x over previous
#include <cuda_runtime.h>
#include <mma.h>
#include <math.h>

#define NATOMS 1048576
#define BMOL   16384
#define DIM    128
#define STEPS  8

#define ATT_THREADS 256
#define SMAX  176      // atoms cached in dynamic SMEM per block (P(cnt>176) ~ 0 for Poisson(64))
#define SCMAX 2048     // scores held in static SMEM up to this count

// ---------------- scratch (static device allocations only) ----------------
__device__ float g_carry[BMOL * DIM];          // 8 MB
__device__ float g_mem  [BMOL * DIM];          // 8 MB
__device__ float g_cse  [BMOL * 2 * DIM];      // 16 MB
__device__ float g_z    [BMOL * 4 * DIM];      // 32 MB
__device__ int   g_segstart[BMOL + 1];
__device__ float g_scores[NATOMS];             // fallback if a segment is huge

// ---------------- init ----------------
__global__ void init_state() {
    int i = blockIdx.x * blockDim.x + threadIdx.x;
    if (i < BMOL * DIM) { g_carry[i] = 0.f; g_mem[i] = 0.f; }
}

// seg_start[b] = lower_bound(idx, b); idx is sorted
__global__ void seg_start_kernel(const int* __restrict__ idx) {
    int b = blockIdx.x * blockDim.x + threadIdx.x;
    if (b > BMOL) return;
    int lo = 0, hi = NATOMS;
    while (lo < hi) {
        int mid = (lo + hi) >> 1;
        if (idx[mid] < b) lo = mid + 1; else hi = mid;
    }
    g_segstart[b] = lo;
}

// ---------------- fused per-molecule attention ----------------
// one block per molecule: load segment atoms into SMEM once, compute scores,
// segment softmax, readout; write cse row = [carry | readout]
__global__ void __launch_bounds__(ATT_THREADS) attn_kernel(
    const float4* __restrict__ F4, float* __restrict__ out) {
    int b    = blockIdx.x;
    int tid  = threadIdx.x;
    int lane = tid & 31;
    int wid  = tid >> 5;

    __shared__ float  carry_s[DIM];
    __shared__ float  sc_s[SCMAX];
    __shared__ __align__(16) float4 part[8][32];   // per-warp readout partials
    __shared__ float  red[8];
    __shared__ float  bc[2];
    extern __shared__ float4 Fs[];                 // SMAX * 32 float4

    int s = g_segstart[b];
    int e = g_segstart[b + 1];
    int cnt = e - s;

    if (tid < DIM) carry_s[tid] = g_carry[b * DIM + tid];
    __syncthreads();

    if (cnt <= 0) {  // empty segment: readout = 0
        if (tid < DIM) out[(size_t)b * 2 * DIM + tid] = carry_s[tid];
        else           out[(size_t)b * 2 * DIM + tid] = 0.f;
        return;
    }

    bool cached = (cnt <= SMAX);
    if (cached) {
        int tot = cnt * 32;
        for (int i = tid; i < tot; i += ATT_THREADS)
            Fs[i] = F4[(size_t)s * 32 + i];
    }
    float* sc = (cnt <= SCMAX) ? sc_s : (g_scores + s);
    __syncthreads();

    float4 c4 = ((const float4*)carry_s)[lane];

    // scores: one warp per atom
    for (int a = wid; a < cnt; a += 8) {
        float4 f = cached ? Fs[a * 32 + lane] : F4[(size_t)(s + a) * 32 + lane];
        float v = f.x * c4.x + f.y * c4.y + f.z * c4.z + f.w * c4.w;
        #pragma unroll
        for (int o = 16; o > 0; o >>= 1) v += __shfl_xor_sync(0xffffffffu, v, o);
        if (lane == 0) sc[a] = v;
    }
    __syncthreads();

    // segment max
    float m = -INFINITY;
    for (int i = tid; i < cnt; i += ATT_THREADS) m = fmaxf(m, sc[i]);
    #pragma unroll
    for (int o = 16; o > 0; o >>= 1) m = fmaxf(m, __shfl_xor_sync(0xffffffffu, m, o));
    if (lane == 0) red[wid] = m;
    __syncthreads();
    if (tid == 0) {
        float mm = red[0];
        #pragma unroll
        for (int w = 1; w < 8; w++) mm = fmaxf(mm, red[w]);
        bc[0] = mm;
    }
    __syncthreads();
    float smax = bc[0];

    // exp + segment sum
    float ssum = 0.f;
    for (int i = tid; i < cnt; i += ATT_THREADS) {
        float ev = expf(sc[i] - smax);
        sc[i] = ev;
        ssum += ev;
    }
    #pragma unroll
    for (int o = 16; o > 0; o >>= 1) ssum += __shfl_xor_sync(0xffffffffu, ssum, o);
    if (lane == 0) red[wid] = ssum;
    __syncthreads();
    if (tid == 0) {
        float t = 0.f;
        #pragma unroll
        for (int w = 0; w < 8; w++) t += red[w];
        bc[1] = t;
    }
    __syncthreads();
    float inv = 1.0f / bc[1];

    // readout: warp-strided accumulation over atoms
    float4 acc = make_float4(0.f, 0.f, 0.f, 0.f);
    for (int a = wid; a < cnt; a += 8) {
        float  co = sc[a] * inv;
        float4 f  = cached ? Fs[a * 32 + lane] : F4[(size_t)(s + a) * 32 + lane];
        acc.x += co * f.x; acc.y += co * f.y; acc.z += co * f.z; acc.w += co * f.w;
    }
    part[wid][lane] = acc;
    __syncthreads();

    if (tid < DIM) {
        out[(size_t)b * 2 * DIM + tid] = carry_s[tid];
    } else {
        int d = tid - DIM;                         // 0..127
        const float* pf = (const float*)part;      // [8][128]
        float sum = 0.f;
        #pragma unroll
        for (int w = 0; w < 8; w++) sum += pf[w * 128 + d];
        out[(size_t)b * 2 * DIM + DIM + d] = sum;
    }
}

// ---------------- 3xTF32 GEMM: g_z = X[BMOL,256] @ W[256,512] ----------------
using namespace nvcuda;
#define GEMM_THREADS 128

__global__ void __launch_bounds__(GEMM_THREADS) gemm_kernel(
    const float* __restrict__ X, const float* __restrict__ W) {
    int bm = blockIdx.x * 64;
    int bn = blockIdx.y * 64;

    __shared__ __align__(16) float Ah[64][36], Al[64][36];
    __shared__ __align__(16) float Bh[32][72], Bl[32][72];

    wmma::fragment<wmma::accumulator, 16, 16, 8, float> acc[2][2];
    #pragma unroll
    for (int i = 0; i < 2; i++)
        #pragma unroll
        for (int j = 0; j < 2; j++) wmma::fill_fragment(acc[i][j], 0.f);

    int wid = threadIdx.x >> 5;
    int wm = (wid >> 1) * 32;
    int wn = (wid & 1) * 32;

    for (int k0 = 0; k0 < 256; k0 += 32) {
        for (int i = threadIdx.x; i < 64 * 32; i += GEMM_THREADS) {
            int r = i >> 5, c = i & 31;
            float v = X[(size_t)(bm + r) * 256 + k0 + c];
            float h = wmma::__float_to_tf32(v);
            Ah[r][c] = h;
            Al[r][c] = wmma::__float_to_tf32(v - h);
        }
        for (int i = threadIdx.x; i < 32 * 64; i += GEMM_THREADS) {
            int r = i >> 6, c = i & 63;
            float v = W[(size_t)(k0 + r) * 512 + bn + c];
            float h = wmma::__float_to_tf32(v);
            Bh[r][c] = h;
            Bl[r][c] = wmma::__float_to_tf32(v - h);
        }
        __syncthreads();

        #pragma unroll
        for (int kk = 0; kk < 32; kk += 8) {
            wmma::fragment<wmma::matrix_a, 16, 16, 8, wmma::precision::tf32, wmma::row_major> ah[2], al[2];
            wmma::fragment<wmma::matrix_b, 16, 16, 8, wmma::precision::tf32, wmma::row_major> bh[2], bl[2];
            #pragma unroll
            for (int i = 0; i < 2; i++) {
                wmma::load_matrix_sync(ah[i], &Ah[wm + i * 16][kk], 36);
                wmma::load_matrix_sync(al[i], &Al[wm + i * 16][kk], 36);
            }
            #pragma unroll
            for (int j = 0; j < 2; j++) {
                wmma::load_matrix_sync(bh[j], &Bh[kk][wn + j * 16], 72);
                wmma::load_matrix_sync(bl[j], &Bl[kk][wn + j * 16], 72);
            }
            #pragma unroll
            for (int i = 0; i < 2; i++)
                #pragma unroll
                for (int j = 0; j < 2; j++) {
                    wmma::mma_sync(acc[i][j], ah[i], bh[j], acc[i][j]);
                    wmma::mma_sync(acc[i][j], ah[i], bl[j], acc[i][j]);
                    wmma::mma_sync(acc[i][j], al[i], bh[j], acc[i][j]);
                }
        }
        __syncthreads();
    }

    #pragma unroll
    for (int i = 0; i < 2; i++)
        #pragma unroll
        for (int j = 0; j < 2; j++)
            wmma::store_matrix_sync(&g_z[(size_t)(bm + wm + i * 16) * 512 + bn + wn + j * 16],
                                    acc[i][j], 512, wmma::mem_row_major);
}

// ---------------- LSTM pointwise ----------------
__global__ void lstm_kernel(const float* __restrict__ bias) {
    int i = blockIdx.x * blockDim.x + threadIdx.x;
    if (i >= BMOL * DIM) return;
    int b = i >> 7;
    int j = i & 127;
    const float* zr = g_z + (size_t)b * 512;
    float u = zr[j]       + bias[j];
    float f = zr[128 + j] + bias[128 + j];
    float c = zr[256 + j] + bias[256 + j];
    float o = zr[384 + j] + bias[384 + j];
    float su = 1.f / (1.f + expf(-u));
    float sf = 1.f / (1.f + expf(-f));
    float so = 1.f / (1.f + expf(-o));
    float mem = sf * g_mem[i] + su * tanhf(c);
    g_mem[i]   = mem;
    g_carry[i] = so * tanhf(mem);
}

// ---------------- launch ----------------
extern "C" void kernel_launch(void* const* d_in, const int* in_sizes, int n_in,
                              void* d_out, int out_size) {
    const float* F    = (const float*)d_in[0];
    const int*   idx  = (const int*)d_in[1];
    const float* W    = (const float*)d_in[2];
    const float* bias = (const float*)d_in[3];
    float* out = (float*)d_out;

    cudaFuncSetAttribute(attn_kernel, cudaFuncAttributeMaxDynamicSharedMemorySize,
                         SMAX * 32 * (int)sizeof(float4));

    void* csep = nullptr;
    cudaGetSymbolAddress(&csep, g_cse);
    float* cse = (float*)csep;

    init_state<<<(BMOL * DIM + 255) / 256, 256>>>();
    seg_start_kernel<<<(BMOL + 1 + 255) / 256, 256>>>(idx);

    for (int t = 0; t < STEPS; t++) {
        float* o = (t == STEPS - 1) ? out : cse;
        attn_kernel<<<BMOL, ATT_THREADS, SMAX * 32 * sizeof(float4)>>>(
            (const float4*)F, o);
        if (t < STEPS - 1) {
            dim3 g(BMOL / 64, 512 / 64);
            gemm_kernel<<<g, GEMM_THREADS>>>(cse, W);
            lstm_kernel<<<(BMOL * DIM + 255) / 256, 256>>>(bias);
        }
    }
}

// round 3
// speedup vs baseline: 1.3666x; 1.3376x over previous
#include <cuda_runtime.h>
#include <cuda_fp16.h>
#include <mma.h>
#include <math.h>

#define NATOMS 1048576
#define BMOL   16384
#define DIM    128
#define STEPS  8

#define ATT_THREADS 256
#define SMAX  176      // atoms cached per block (counts ~Poisson(64); 176 = +14 sigma)
#define SCMAX 256      // scores held in static SMEM up to this count

// ---------------- scratch (static device arrays only) ----------------
__device__ float g_carry[BMOL * DIM];          // 8 MB
__device__ float g_mem  [BMOL * DIM];          // 8 MB
__device__ float g_cse  [BMOL * 2 * DIM];      // 16 MB
__device__ float g_z    [BMOL * 4 * DIM];      // 32 MB
__device__ int   g_segstart[BMOL + 1];
__device__ float g_scores[NATOMS];             // fallback for huge segments
__device__ __half g_Fh[(size_t)NATOMS * DIM];  // 256 MB fp16 copy of features

// ---------------- init ----------------
__global__ void init_state() {
    int i = blockIdx.x * blockDim.x + threadIdx.x;
    if (i < BMOL * DIM) { g_carry[i] = 0.f; g_mem[i] = 0.f; }
}

// convert features fp32 -> fp16 (once). 8 floats per thread.
__global__ void convert_kernel(const float4* __restrict__ F4) {
    size_t i = (size_t)blockIdx.x * blockDim.x + threadIdx.x;   // index of 8-float group
    size_t total = (size_t)NATOMS * DIM / 8;
    if (i >= total) return;
    float4 a = F4[i * 2];
    float4 b = F4[i * 2 + 1];
    uint4 o;
    __half2 h0 = __floats2half2_rn(a.x, a.y);
    __half2 h1 = __floats2half2_rn(a.z, a.w);
    __half2 h2 = __floats2half2_rn(b.x, b.y);
    __half2 h3 = __floats2half2_rn(b.z, b.w);
    o.x = *(unsigned*)&h0; o.y = *(unsigned*)&h1;
    o.z = *(unsigned*)&h2; o.w = *(unsigned*)&h3;
    ((uint4*)g_Fh)[i] = o;
}

// seg_start[b] = lower_bound(idx, b); idx is sorted
__global__ void seg_start_kernel(const int* __restrict__ idx) {
    int b = blockIdx.x * blockDim.x + threadIdx.x;
    if (b > BMOL) return;
    int lo = 0, hi = NATOMS;
    while (lo < hi) {
        int mid = (lo + hi) >> 1;
        if (idx[mid] < b) lo = mid + 1; else hi = mid;
    }
    g_segstart[b] = lo;
}

// ---------------- fused per-molecule attention (fp16 features) ----------------
__device__ __forceinline__ float4 h8_to_f4_dot_load(uint2 p, float4& lo, float4& hi) {
    __half2 a = *(__half2*)&p.x;   // elems 0,1
    __half2 b = *(__half2*)&p.y;   // elems 2,3
    float2 fa = __half22float2(a);
    float2 fb = __half22float2(b);
    lo = make_float4(fa.x, fa.y, fb.x, fb.y);
    return lo;
}

__global__ void __launch_bounds__(ATT_THREADS) attn_kernel(
    float* __restrict__ out) {
    int b    = blockIdx.x;
    int tid  = threadIdx.x;
    int lane = tid & 31;
    int wid  = tid >> 5;

    __shared__ float  carry_s[DIM];
    __shared__ float  sc_s[SCMAX];
    __shared__ __align__(16) float4 part[8][32];
    __shared__ float  red[8];
    __shared__ float  bc[2];
    extern __shared__ uint2 Fs[];                 // SMAX * 32 uint2 (4 halves each)

    const uint2* F2 = (const uint2*)g_Fh;         // 32 uint2 per atom row

    int s = g_segstart[b];
    int e = g_segstart[b + 1];
    int cnt = e - s;

    if (tid < DIM) carry_s[tid] = g_carry[b * DIM + tid];
    __syncthreads();

    if (cnt <= 0) {
        if (tid < DIM) out[(size_t)b * 2 * DIM + tid] = carry_s[tid];
        else           out[(size_t)b * 2 * DIM + tid] = 0.f;
        return;
    }

    bool cached = (cnt <= SMAX);
    if (cached) {
        int tot = cnt * 32;
        const uint2* src = F2 + (size_t)s * 32;
        for (int i = tid; i < tot; i += ATT_THREADS)
            Fs[i] = src[i];
    }
    float* sc = (cnt <= SCMAX) ? sc_s : (g_scores + s);
    __syncthreads();

    float4 c4 = ((const float4*)carry_s)[lane];

    // scores: one warp per atom
    for (int a = wid; a < cnt; a += 8) {
        uint2 p = cached ? Fs[a * 32 + lane] : F2[(size_t)(s + a) * 32 + lane];
        float2 fa = __half22float2(*(__half2*)&p.x);
        float2 fb = __half22float2(*(__half2*)&p.y);
        float v = fa.x * c4.x + fa.y * c4.y + fb.x * c4.z + fb.y * c4.w;
        #pragma unroll
        for (int o = 16; o > 0; o >>= 1) v += __shfl_xor_sync(0xffffffffu, v, o);
        if (lane == 0) sc[a] = v;
    }
    __syncthreads();

    // segment max
    float m = -INFINITY;
    for (int i = tid; i < cnt; i += ATT_THREADS) m = fmaxf(m, sc[i]);
    #pragma unroll
    for (int o = 16; o > 0; o >>= 1) m = fmaxf(m, __shfl_xor_sync(0xffffffffu, m, o));
    if (lane == 0) red[wid] = m;
    __syncthreads();
    if (tid == 0) {
        float mm = red[0];
        #pragma unroll
        for (int w = 1; w < 8; w++) mm = fmaxf(mm, red[w]);
        bc[0] = mm;
    }
    __syncthreads();
    float smax = bc[0];

    // exp + segment sum
    float ssum = 0.f;
    for (int i = tid; i < cnt; i += ATT_THREADS) {
        float ev = expf(sc[i] - smax);
        sc[i] = ev;
        ssum += ev;
    }
    #pragma unroll
    for (int o = 16; o > 0; o >>= 1) ssum += __shfl_xor_sync(0xffffffffu, ssum, o);
    if (lane == 0) red[wid] = ssum;
    __syncthreads();
    if (tid == 0) {
        float t = 0.f;
        #pragma unroll
        for (int w = 0; w < 8; w++) t += red[w];
        bc[1] = t;
    }
    __syncthreads();
    float inv = 1.0f / bc[1];

    // readout
    float4 acc = make_float4(0.f, 0.f, 0.f, 0.f);
    for (int a = wid; a < cnt; a += 8) {
        float  co = sc[a] * inv;
        uint2 p = cached ? Fs[a * 32 + lane] : F2[(size_t)(s + a) * 32 + lane];
        float2 fa = __half22float2(*(__half2*)&p.x);
        float2 fb = __half22float2(*(__half2*)&p.y);
        acc.x += co * fa.x; acc.y += co * fa.y;
        acc.z += co * fb.x; acc.w += co * fb.y;
    }
    part[wid][lane] = acc;
    __syncthreads();

    if (tid < DIM) {
        out[(size_t)b * 2 * DIM + tid] = carry_s[tid];
    } else {
        int d = tid - DIM;
        const float* pf = (const float*)part;
        float sum = 0.f;
        #pragma unroll
        for (int w = 0; w < 8; w++) sum += pf[w * 128 + d];
        out[(size_t)b * 2 * DIM + DIM + d] = sum;
    }
}

// ---------------- 3xTF32 GEMM, 128x128 tiles: g_z = X[BMOL,256] @ W[256,512] ----
using namespace nvcuda;
#define GEMM_THREADS 256
// smem layout (floats): Ah[128][36], Al[128][36], Bh[32][132], Bl[32][132]
#define A_LD 36
#define B_LD 132
#define A_SZ (128 * A_LD)
#define B_SZ (32 * B_LD)
#define GEMM_SMEM ((2 * A_SZ + 2 * B_SZ) * sizeof(float))

__global__ void __launch_bounds__(GEMM_THREADS) gemm_kernel(
    const float* __restrict__ X, const float* __restrict__ W) {
    int bm = blockIdx.x * 128;
    int bn = blockIdx.y * 128;

    extern __shared__ float sm[];
    float* Ah = sm;
    float* Al = Ah + A_SZ;
    float* Bh = Al + A_SZ;
    float* Bl = Bh + B_SZ;

    wmma::fragment<wmma::accumulator, 16, 16, 8, float> acc[2][4];
    #pragma unroll
    for (int i = 0; i < 2; i++)
        #pragma unroll
        for (int j = 0; j < 4; j++) wmma::fill_fragment(acc[i][j], 0.f);

    int wid = threadIdx.x >> 5;
    int wm = (wid >> 1) * 32;      // 4 warp-rows
    int wn = (wid & 1) * 64;      // 2 warp-cols

    for (int k0 = 0; k0 < 256; k0 += 32) {
        // A tile: 128x32
        #pragma unroll
        for (int i = threadIdx.x; i < 128 * 32; i += GEMM_THREADS) {
            int r = i >> 5, c = i & 31;
            float v = X[(size_t)(bm + r) * 256 + k0 + c];
            float h = wmma::__float_to_tf32(v);
            Ah[r * A_LD + c] = h;
            Al[r * A_LD + c] = wmma::__float_to_tf32(v - h);
        }
        // B tile: 32x128
        #pragma unroll
        for (int i = threadIdx.x; i < 32 * 128; i += GEMM_THREADS) {
            int r = i >> 7, c = i & 127;
            float v = W[(size_t)(k0 + r) * 512 + bn + c];
            float h = wmma::__float_to_tf32(v);
            Bh[r * B_LD + c] = h;
            Bl[r * B_LD + c] = wmma::__float_to_tf32(v - h);
        }
        __syncthreads();

        #pragma unroll
        for (int kk = 0; kk < 32; kk += 8) {
            wmma::fragment<wmma::matrix_a, 16, 16, 8, wmma::precision::tf32, wmma::row_major> ah[2], al[2];
            wmma::fragment<wmma::matrix_b, 16, 16, 8, wmma::precision::tf32, wmma::row_major> bh[4], bl[4];
            #pragma unroll
            for (int i = 0; i < 2; i++) {
                wmma::load_matrix_sync(ah[i], &Ah[(wm + i * 16) * A_LD + kk], A_LD);
                wmma::load_matrix_sync(al[i], &Al[(wm + i * 16) * A_LD + kk], A_LD);
            }
            #pragma unroll
            for (int j = 0; j < 4; j++) {
                wmma::load_matrix_sync(bh[j], &Bh[kk * B_LD + wn + j * 16], B_LD);
                wmma::load_matrix_sync(bl[j], &Bl[kk * B_LD + wn + j * 16], B_LD);
            }
            #pragma unroll
            for (int i = 0; i < 2; i++)
                #pragma unroll
                for (int j = 0; j < 4; j++) {
                    wmma::mma_sync(acc[i][j], ah[i], bh[j], acc[i][j]);
                    wmma::mma_sync(acc[i][j], ah[i], bl[j], acc[i][j]);
                    wmma::mma_sync(acc[i][j], al[i], bh[j], acc[i][j]);
                }
        }
        __syncthreads();
    }

    #pragma unroll
    for (int i = 0; i < 2; i++)
        #pragma unroll
        for (int j = 0; j < 4; j++)
            wmma::store_matrix_sync(&g_z[(size_t)(bm + wm + i * 16) * 512 + bn + wn + j * 16],
                                    acc[i][j], 512, wmma::mem_row_major);
}

// ---------------- LSTM pointwise ----------------
__global__ void lstm_kernel(const float* __restrict__ bias) {
    int i = blockIdx.x * blockDim.x + threadIdx.x;
    if (i >= BMOL * DIM) return;
    int b = i >> 7;
    int j = i & 127;
    const float* zr = g_z + (size_t)b * 512;
    float u = zr[j]       + bias[j];
    float f = zr[128 + j] + bias[128 + j];
    float c = zr[256 + j] + bias[256 + j];
    float o = zr[384 + j] + bias[384 + j];
    float su = 1.f / (1.f + expf(-u));
    float sf = 1.f / (1.f + expf(-f));
    float so = 1.f / (1.f + expf(-o));
    float mem = sf * g_mem[i] + su * tanhf(c);
    g_mem[i]   = mem;
    g_carry[i] = so * tanhf(mem);
}

// ---------------- launch ----------------
extern "C" void kernel_launch(void* const* d_in, const int* in_sizes, int n_in,
                              void* d_out, int out_size) {
    const float* F    = (const float*)d_in[0];
    const int*   idx  = (const int*)d_in[1];
    const float* W    = (const float*)d_in[2];
    const float* bias = (const float*)d_in[3];
    float* out = (float*)d_out;

    static bool attr_done = false;
    if (!attr_done) {
        cudaFuncSetAttribute(attn_kernel, cudaFuncAttributeMaxDynamicSharedMemorySize,
                             SMAX * 32 * (int)sizeof(uint2));
        cudaFuncSetAttribute(gemm_kernel, cudaFuncAttributeMaxDynamicSharedMemorySize,
                             (int)GEMM_SMEM);
        attr_done = true;
    }

    void* csep = nullptr;
    cudaGetSymbolAddress(&csep, g_cse);
    float* cse = (float*)csep;

    init_state<<<(BMOL * DIM + 255) / 256, 256>>>();
    convert_kernel<<<(int)(((size_t)NATOMS * DIM / 8 + 255) / 256), 256>>>((const float4*)F);
    seg_start_kernel<<<(BMOL + 1 + 255) / 256, 256>>>(idx);

    for (int t = 0; t < STEPS; t++) {
        float* o = (t == STEPS - 1) ? out : cse;
        attn_kernel<<<BMOL, ATT_THREADS, SMAX * 32 * sizeof(uint2)>>>(o);
        if (t < STEPS - 1) {
            dim3 g(BMOL / 128, 512 / 128);
            gemm_kernel<<<g, GEMM_THREADS, GEMM_SMEM>>>(cse, W);
            lstm_kernel<<<(BMOL * DIM + 255) / 256, 256>>>(bias);
        }
    }
}

// round 4
// speedup vs baseline: 2.7020x; 1.9772x over previous
#include <cuda_runtime.h>
#include <cuda_fp16.h>
#include <mma.h>
#include <math.h>

#define NATOMS 1048576
#define BMOL   16384
#define DIM    128
#define STEPS  8

#define ATT_THREADS 256
#define SCMAX 512      // scores in SMEM up to this count (max seg ~Poisson(64))

// ---------------- scratch (static device arrays only) ----------------
__device__ float g_carry[BMOL * DIM];
__device__ float g_mem  [BMOL * DIM];
__device__ float g_cse  [BMOL * 2 * DIM];
__device__ float g_z    [BMOL * 4 * DIM];
__device__ int   g_segstart[BMOL + 1];
__device__ float g_scores[NATOMS];             // fallback for huge segments
__device__ __half g_Fh[(size_t)NATOMS * DIM];  // 256 MB fp16 features

// ---------------- init ----------------
__global__ void init_state() {
    int i = blockIdx.x * blockDim.x + threadIdx.x;
    if (i < BMOL * DIM) { g_carry[i] = 0.f; g_mem[i] = 0.f; }
}

// fp32 -> fp16 feature copy (streaming, once per launch)
__global__ void convert_kernel(const float4* __restrict__ F4) {
    size_t i = (size_t)blockIdx.x * blockDim.x + threadIdx.x;
    size_t total = (size_t)NATOMS * DIM / 8;
    if (i >= total) return;
    float4 a = F4[i * 2];
    float4 b = F4[i * 2 + 1];
    __half2 h0 = __floats2half2_rn(a.x, a.y);
    __half2 h1 = __floats2half2_rn(a.z, a.w);
    __half2 h2 = __floats2half2_rn(b.x, b.y);
    __half2 h3 = __floats2half2_rn(b.z, b.w);
    uint4 o;
    o.x = *(unsigned*)&h0; o.y = *(unsigned*)&h1;
    o.z = *(unsigned*)&h2; o.w = *(unsigned*)&h3;
    ((uint4*)g_Fh)[i] = o;
}

__global__ void seg_start_kernel(const int* __restrict__ idx) {
    int b = blockIdx.x * blockDim.x + threadIdx.x;
    if (b > BMOL) return;
    int lo = 0, hi = NATOMS;
    while (lo < hi) {
        int mid = (lo + hi) >> 1;
        if (idx[mid] < b) lo = mid + 1; else hi = mid;
    }
    g_segstart[b] = lo;
}

// ---------------- fused per-molecule attention (streaming fp16) ----------------
// One block per molecule. No feature SMEM staging: rely on L1 for 2nd pass.
// Warp processes 2 atoms per iteration: lanes 0-15 -> atom a0, 16-31 -> a0+1,
// each lane handles 8 consecutive feature dims via one LDG.128.
__device__ __forceinline__ void h8_to_f(uint4 p, float* f) {
    float2 f0 = __half22float2(*(__half2*)&p.x);
    float2 f1 = __half22float2(*(__half2*)&p.y);
    float2 f2 = __half22float2(*(__half2*)&p.z);
    float2 f3 = __half22float2(*(__half2*)&p.w);
    f[0] = f0.x; f[1] = f0.y; f[2] = f1.x; f[3] = f1.y;
    f[4] = f2.x; f[5] = f2.y; f[6] = f3.x; f[7] = f3.y;
}

__global__ void __launch_bounds__(ATT_THREADS) attn_kernel(float* __restrict__ out) {
    int b    = blockIdx.x;
    int tid  = threadIdx.x;
    int lane = tid & 31;
    int wid  = tid >> 5;

    __shared__ float carry_s[DIM];
    __shared__ float sc_s[SCMAX];
    __shared__ float part[8][16][8];   // [warp][lane-group][8 dims]
    __shared__ float red[8];
    __shared__ float bc[2];

    int s = g_segstart[b];
    int e = g_segstart[b + 1];
    int cnt = e - s;

    if (tid < DIM) carry_s[tid] = g_carry[b * DIM + tid];
    __syncthreads();

    if (cnt <= 0) {
        if (tid < DIM) out[(size_t)b * 2 * DIM + tid] = carry_s[tid];
        else           out[(size_t)b * 2 * DIM + tid] = 0.f;
        return;
    }

    float* sc = (cnt <= SCMAX) ? sc_s : (g_scores + s);

    const uint4* F4h = (const uint4*)g_Fh;   // 16 uint4 per atom row
    int half_id = lane >> 4;                  // 0 or 1
    int sub     = lane & 15;                  // dim chunk within row
    float c8[8];
    #pragma unroll
    for (int k = 0; k < 8; k++) c8[k] = carry_s[sub * 8 + k];

    // ---- scores ----
    for (int a0 = wid * 2; a0 < cnt; a0 += 16) {
        int a = a0 + half_id;
        float v = 0.f;
        if (a < cnt) {
            uint4 p = F4h[(size_t)(s + a) * 16 + sub];
            float f[8]; h8_to_f(p, f);
            #pragma unroll
            for (int k = 0; k < 8; k++) v += f[k] * c8[k];
        }
        #pragma unroll
        for (int o = 8; o > 0; o >>= 1) v += __shfl_xor_sync(0xffffffffu, v, o);
        if (sub == 0 && a < cnt) sc[a] = v;
    }
    __syncthreads();

    // ---- segment max ----
    float m = -INFINITY;
    for (int i = tid; i < cnt; i += ATT_THREADS) m = fmaxf(m, sc[i]);
    #pragma unroll
    for (int o = 16; o > 0; o >>= 1) m = fmaxf(m, __shfl_xor_sync(0xffffffffu, m, o));
    if (lane == 0) red[wid] = m;
    __syncthreads();
    if (tid == 0) {
        float mm = red[0];
        #pragma unroll
        for (int w = 1; w < 8; w++) mm = fmaxf(mm, red[w]);
        bc[0] = mm;
    }
    __syncthreads();
    float smax = bc[0];

    // ---- exp + segment sum ----
    float ssum = 0.f;
    for (int i = tid; i < cnt; i += ATT_THREADS) {
        float ev = expf(sc[i] - smax);
        sc[i] = ev;
        ssum += ev;
    }
    #pragma unroll
    for (int o = 16; o > 0; o >>= 1) ssum += __shfl_xor_sync(0xffffffffu, ssum, o);
    if (lane == 0) red[wid] = ssum;
    __syncthreads();
    if (tid == 0) {
        float t = 0.f;
        #pragma unroll
        for (int w = 0; w < 8; w++) t += red[w];
        bc[1] = t;
    }
    __syncthreads();
    float inv = 1.0f / bc[1];

    // ---- readout ----
    float acc[8];
    #pragma unroll
    for (int k = 0; k < 8; k++) acc[k] = 0.f;
    for (int a0 = wid * 2; a0 < cnt; a0 += 16) {
        int a = a0 + half_id;
        if (a < cnt) {
            float co = sc[a] * inv;
            uint4 p = F4h[(size_t)(s + a) * 16 + sub];
            float f[8]; h8_to_f(p, f);
            #pragma unroll
            for (int k = 0; k < 8; k++) acc[k] += co * f[k];
        }
    }
    #pragma unroll
    for (int k = 0; k < 8; k++) acc[k] += __shfl_xor_sync(0xffffffffu, acc[k], 16);
    if (half_id == 0) {
        #pragma unroll
        for (int k = 0; k < 8; k++) part[wid][sub][k] = acc[k];
    }
    __syncthreads();

    if (tid < DIM) {
        out[(size_t)b * 2 * DIM + tid] = carry_s[tid];
    } else {
        int d = tid - DIM;
        float sum = 0.f;
        #pragma unroll
        for (int w = 0; w < 8; w++) sum += part[w][d >> 3][d & 7];
        out[(size_t)b * 2 * DIM + DIM + d] = sum;
    }
}

// ---------------- fp16-split GEMM: g_z = X[BMOL,256] @ W[256,512] ----------------
// x = hi + lo (both fp16); D = Xh*Wh + Xh*Wl + Xl*Wh, fp32 accumulate.
// Error per product ~ eps_fp16^2 ~ 2.4e-7 -> negligible.
using namespace nvcuda;
#define GEMM_THREADS 256
#define A_LDH 72
#define B_LDH 136
#define AH_SZ (128 * A_LDH)     // halves
#define BH_SZ (64 * B_LDH)
#define GEMM_SMEM ((2 * AH_SZ + 2 * BH_SZ) * sizeof(__half))

__global__ void __launch_bounds__(GEMM_THREADS) gemm_kernel(
    const float4* __restrict__ X4, const float4* __restrict__ W4) {
    int bm = blockIdx.x * 128;
    int bn = blockIdx.y * 128;

    extern __shared__ __half smh[];
    __half* Ah = smh;
    __half* Al = Ah + AH_SZ;
    __half* Bh = Al + AH_SZ;
    __half* Bl = Bh + BH_SZ;

    wmma::fragment<wmma::accumulator, 16, 16, 16, float> acc[2][4];
    #pragma unroll
    for (int i = 0; i < 2; i++)
        #pragma unroll
        for (int j = 0; j < 4; j++) wmma::fill_fragment(acc[i][j], 0.f);

    int wid = threadIdx.x >> 5;
    int wm = (wid >> 1) * 32;   // 4 warp rows of 32
    int wn = (wid & 1) * 64;   // 2 warp cols of 64

    for (int k0 = 0; k0 < 256; k0 += 64) {
        // A tile: 128 x 64 floats -> hi/lo halves. 16 float4 per row.
        for (int i = threadIdx.x; i < 128 * 16; i += GEMM_THREADS) {
            int r = i >> 4, c = i & 15;
            float4 v = X4[(size_t)(bm + r) * 64 + (k0 >> 2) + c];
            float vv[4] = {v.x, v.y, v.z, v.w};
            #pragma unroll
            for (int j = 0; j < 4; j++) {
                __half h = __float2half_rn(vv[j]);
                Ah[r * A_LDH + c * 4 + j] = h;
                Al[r * A_LDH + c * 4 + j] = __float2half_rn(vv[j] - __half2float(h));
            }
        }
        // B tile: 64 x 128 floats. 32 float4 per row (W row = 512 floats = 128 f4).
        for (int i = threadIdx.x; i < 64 * 32; i += GEMM_THREADS) {
            int r = i >> 5, c = i & 31;
            float4 v = W4[(size_t)(k0 + r) * 128 + (bn >> 2) + c];
            float vv[4] = {v.x, v.y, v.z, v.w};
            #pragma unroll
            for (int j = 0; j < 4; j++) {
                __half h = __float2half_rn(vv[j]);
                Bh[r * B_LDH + c * 4 + j] = h;
                Bl[r * B_LDH + c * 4 + j] = __float2half_rn(vv[j] - __half2float(h));
            }
        }
        __syncthreads();

        #pragma unroll
        for (int kk = 0; kk < 64; kk += 16) {
            wmma::fragment<wmma::matrix_a, 16, 16, 16, __half, wmma::row_major> ah[2], al[2];
            wmma::fragment<wmma::matrix_b, 16, 16, 16, __half, wmma::row_major> bh[4], bl[4];
            #pragma unroll
            for (int i = 0; i < 2; i++) {
                wmma::load_matrix_sync(ah[i], &Ah[(wm + i * 16) * A_LDH + kk], A_LDH);
                wmma::load_matrix_sync(al[i], &Al[(wm + i * 16) * A_LDH + kk], A_LDH);
            }
            #pragma unroll
            for (int j = 0; j < 4; j++) {
                wmma::load_matrix_sync(bh[j], &Bh[kk * B_LDH + wn + j * 16], B_LDH);
                wmma::load_matrix_sync(bl[j], &Bl[kk * B_LDH + wn + j * 16], B_LDH);
            }
            #pragma unroll
            for (int i = 0; i < 2; i++)
                #pragma unroll
                for (int j = 0; j < 4; j++) {
                    wmma::mma_sync(acc[i][j], ah[i], bh[j], acc[i][j]);
                    wmma::mma_sync(acc[i][j], ah[i], bl[j], acc[i][j]);
                    wmma::mma_sync(acc[i][j], al[i], bh[j], acc[i][j]);
                }
        }
        __syncthreads();
    }

    #pragma unroll
    for (int i = 0; i < 2; i++)
        #pragma unroll
        for (int j = 0; j < 4; j++)
            wmma::store_matrix_sync(&g_z[(size_t)(bm + wm + i * 16) * 512 + bn + wn + j * 16],
                                    acc[i][j], 512, wmma::mem_row_major);
}

// ---------------- LSTM pointwise ----------------
__global__ void lstm_kernel(const float* __restrict__ bias) {
    int i = blockIdx.x * blockDim.x + threadIdx.x;
    if (i >= BMOL * DIM) return;
    int b = i >> 7;
    int j = i & 127;
    const float* zr = g_z + (size_t)b * 512;
    float u = zr[j]       + bias[j];
    float f = zr[128 + j] + bias[128 + j];
    float c = zr[256 + j] + bias[256 + j];
    float o = zr[384 + j] + bias[384 + j];
    float su = 1.f / (1.f + expf(-u));
    float sf = 1.f / (1.f + expf(-f));
    float so = 1.f / (1.f + expf(-o));
    float mem = sf * g_mem[i] + su * tanhf(c);
    g_mem[i]   = mem;
    g_carry[i] = so * tanhf(mem);
}

// ---------------- launch ----------------
extern "C" void kernel_launch(void* const* d_in, const int* in_sizes, int n_in,
                              void* d_out, int out_size) {
    const float* F    = (const float*)d_in[0];
    const int*   idx  = (const int*)d_in[1];
    const float* W    = (const float*)d_in[2];
    const float* bias = (const float*)d_in[3];
    float* out = (float*)d_out;

    static bool attr_done = false;
    if (!attr_done) {
        cudaFuncSetAttribute(gemm_kernel, cudaFuncAttributeMaxDynamicSharedMemorySize,
                             (int)GEMM_SMEM);
        attr_done = true;
    }

    void* csep = nullptr;
    cudaGetSymbolAddress(&csep, g_cse);
    float* cse = (float*)csep;

    init_state<<<(BMOL * DIM + 255) / 256, 256>>>();
    convert_kernel<<<(int)(((size_t)NATOMS * DIM / 8 + 255) / 256), 256>>>((const float4*)F);
    seg_start_kernel<<<(BMOL + 1 + 255) / 256, 256>>>(idx);

    for (int t = 0; t < STEPS; t++) {
        float* o = (t == STEPS - 1) ? out : cse;
        attn_kernel<<<BMOL, ATT_THREADS>>>(o);
        if (t < STEPS - 1) {
            dim3 g(BMOL / 128, 512 / 128);
            gemm_kernel<<<g, GEMM_THREADS, GEMM_SMEM>>>((const float4*)cse, (const float4*)W);
            lstm_kernel<<<(BMOL * DIM + 255) / 256, 256>>>(bias);
        }
    }
}